// round 3
// baseline (speedup 1.0000x reference)
#include <cuda_runtime.h>
#include <cuda_bf16.h>

// IDWT3D: 3D inverse Haar wavelet synthesis, N=256, channels=2.
// Input  x: [1, 128, 128, 128, 16]  (8 octant subbands x 2 channels, channel-stacked)
// Output:  [1, 256, 256, 256, 2]
//
// Per axis (S = A^T, Haar):  out[2i] = r*(a-d), out[2i+1] = r*(a+d); separable
// over 3 axes -> per-voxel 3-level butterfly scaled by r^3 = 2^-1.5.
//
// R2 ncu: 70.9% DRAM, 5794 GB/s, compute idle -> pure HBM-bound.
// R3 changes: 2 adjacent-k voxels per thread (8 front-batched float4 loads,
// 1 KiB contiguous store segments) + __ldcs/__stcs streaming cache hints.

#define NH 128
#define R3c 0.35355339059327378f   // (1/sqrt(2))^3

// Butterfly one voxel's 16 subband values (4 float4s) into the 4 output
// float4s (one per (s1,s2)), fused r^3 scale.
__device__ __forceinline__ void butterfly16(const float4 p0, const float4 p1,
                                            const float4 p2, const float4 p3,
                                            float4 w[2][2])
{
    // v[oct][ch], oct = 4*e1 + 2*e2 + e3
    const float v[8][2] = {
        {p0.x, p0.y}, {p0.z, p0.w},
        {p1.x, p1.y}, {p1.z, p1.w},
        {p2.x, p2.y}, {p2.z, p2.w},
        {p3.x, p3.y}, {p3.z, p3.w}
    };

    float t3[2][2][2][2];   // [e1][e2][s3][ch]
    #pragma unroll
    for (int e1 = 0; e1 < 2; ++e1)
        #pragma unroll
        for (int e2 = 0; e2 < 2; ++e2)
            #pragma unroll
            for (int ch = 0; ch < 2; ++ch) {
                const float lo = v[4*e1 + 2*e2 + 0][ch];
                const float hi = v[4*e1 + 2*e2 + 1][ch];
                t3[e1][e2][0][ch] = lo - hi;
                t3[e1][e2][1][ch] = lo + hi;
            }

    float t2[2][2][2][2];   // [e1][s2][s3][ch]
    #pragma unroll
    for (int e1 = 0; e1 < 2; ++e1)
        #pragma unroll
        for (int s3 = 0; s3 < 2; ++s3)
            #pragma unroll
            for (int ch = 0; ch < 2; ++ch) {
                const float lo = t3[e1][0][s3][ch];
                const float hi = t3[e1][1][s3][ch];
                t2[e1][0][s3][ch] = lo - hi;
                t2[e1][1][s3][ch] = lo + hi;
            }

    #pragma unroll
    for (int s1 = 0; s1 < 2; ++s1)
        #pragma unroll
        for (int s2 = 0; s2 < 2; ++s2) {
            // s1 selects +/- combination of e1
            float o[2][2];  // [s3][ch]
            #pragma unroll
            for (int s3 = 0; s3 < 2; ++s3)
                #pragma unroll
                for (int ch = 0; ch < 2; ++ch) {
                    const float lo = t2[0][s2][s3][ch];
                    const float hi = t2[1][s2][s3][ch];
                    o[s3][ch] = R3c * (s1 ? (lo + hi) : (lo - hi));
                }
            w[s1][s2] = make_float4(o[0][0], o[0][1], o[1][0], o[1][1]);
        }
}

__global__ void __launch_bounds__(256)
idwt3d_haar_kernel(const float* __restrict__ x, float* __restrict__ out)
{
    // One thread = 2 adjacent-k voxels. 128^3/2 = 1,048,576 threads.
    const int t = blockIdx.x * 256 + threadIdx.x;
    const int m = t & 63;             // k pair: k = 2m, 2m+1
    const int j = (t >> 6) & (NH - 1);
    const int i = t >> 13;

    // 32 contiguous floats (2 voxels x 16): 8 float4 loads, front-batched,
    // streaming policy (read-once).
    const float4* __restrict__ xin = reinterpret_cast<const float4*>(x) + (size_t)t * 8;
    const float4 a0 = __ldcs(xin + 0);
    const float4 a1 = __ldcs(xin + 1);
    const float4 a2 = __ldcs(xin + 2);
    const float4 a3 = __ldcs(xin + 3);
    const float4 b0 = __ldcs(xin + 4);
    const float4 b1 = __ldcs(xin + 5);
    const float4 b2 = __ldcs(xin + 6);
    const float4 b3 = __ldcs(xin + 7);

    float4 wa[2][2], wb[2][2];
    butterfly16(a0, a1, a2, a3, wa);   // voxel k = 2m
    butterfly16(b0, b1, b2, b3, wb);   // voxel k = 2m+1

    // out float4 index = ((2i+s1)*256 + (2j+s2))*128 + (2m + q), q in {0,1}.
    // Consecutive threads (m) cover 1 KiB contiguous per (s1,s2) row.
    float4* __restrict__ out4 = reinterpret_cast<float4*>(out);
    const int yb = 2 * i;
    const int xb = 2 * j;
    #pragma unroll
    for (int s1 = 0; s1 < 2; ++s1)
        #pragma unroll
        for (int s2 = 0; s2 < 2; ++s2) {
            const size_t idx = ((size_t)(yb + s1) * 256 + (xb + s2)) * 128 + 2 * m;
            __stcs(out4 + idx,     wa[s1][s2]);
            __stcs(out4 + idx + 1, wb[s1][s2]);
        }
}

extern "C" void kernel_launch(void* const* d_in, const int* in_sizes, int n_in,
                              void* d_out, int out_size)
{
    const float* x = (const float*)d_in[0];   // [1,128,128,128,16] fp32
    float* out = (float*)d_out;               // [1,256,256,256,2] fp32
    (void)in_sizes; (void)n_in; (void)out_size;

    const int threads_total = NH * NH * NH / 2;   // 1,048,576
    idwt3d_haar_kernel<<<threads_total / 256, 256>>>(x, out);
}